// round 6
// baseline (speedup 1.0000x reference)
#include <cuda_runtime.h>
#include <cuda_fp16.h>
#include <cstdint>

// InstantNGPMLP fused on mma.sync m16n8k16 (tcgen05 unavailable: harness
// compiles via compute_103 virtual arch).
// R6 vs R5 (197us, tensor=58.8%, L1=57.1%):
//   - M=32 rows/warp (two m16 fragment sets) -> each B-fragment load feeds
//     6 mma instead of 3 (smem bytes/mma halved)
//   - hi/lo B fragments interleaved as one uint4 -> LDS.128, 88 loads per
//     32-row tile (was 352 LDS.64)
//   - keep 3-term hi/lo fp16 split (rel_err ~5e-7)

#define THREADS 128
#define WARPS 4
#define NROWS 1048576
#define WTILES (NROWS / 32)   // 32768 tiles of 32 rows
#define GRID 592

__device__ __forceinline__ void mma16816(float d[4], const uint32_t* a, uint32_t b0, uint32_t b1) {
    asm volatile(
        "mma.sync.aligned.m16n8k16.row.col.f32.f16.f16.f32 "
        "{%0,%1,%2,%3}, {%4,%5,%6,%7}, {%8,%9}, {%0,%1,%2,%3};"
        : "+f"(d[0]), "+f"(d[1]), "+f"(d[2]), "+f"(d[3])
        : "r"(a[0]), "r"(a[1]), "r"(a[2]), "r"(a[3]), "r"(b0), "r"(b1));
}

__device__ __forceinline__ void pack_hl(float f0, float f1, uint32_t& hi, uint32_t& lo) {
    __half h0 = __float2half_rn(f0);
    __half h1 = __float2half_rn(f1);
    __half l0 = __float2half_rn(f0 - __half2float(h0));
    __half l1 = __float2half_rn(f1 - __half2float(h1));
    hi = (uint32_t)__half_as_ushort(h0) | ((uint32_t)__half_as_ushort(h1) << 16);
    lo = (uint32_t)__half_as_ushort(l0) | ((uint32_t)__half_as_ushort(l1) << 16);
}

// ---- static smem: interleaved hi/lo weight fragments + biases (~44.7 KB) ----
// frag[idx] = { bh0, bh1, bl0, bl1 } for (ks, j, lane)
__shared__ uint4 sf1[512];    // L1: 2ks x 8nf x 32
__shared__ uint4 sf2[1024];   // L2: 4ks x 8nf x 32
__shared__ uint4 sf3[1024];   // L3
__shared__ uint4 sf4[256];    // L4: 4ks x 2nf x 32
__shared__ float sb1[64], sb2[64], sb3[64], sb4[16];

// Stage W (K x N row-major fp32) into interleaved hi/lo B-fragment order.
__device__ void stage(const float* __restrict__ W, int K, int N,
                      uint4* frag, int tid) {
    const int NF = N / 8, total = (K / 16) * NF * 32;
    for (int idx = tid; idx < total; idx += THREADS) {
        int lane = idx & 31, f = idx >> 5;
        int j = f % NF, ks = f / NF;
        int g = lane >> 2, t = lane & 3;
        int n = j * 8 + g;
        int k0 = ks * 16 + 2 * t;
        uint32_t h0, l0, h1, l1;
        pack_hl(W[k0 * N + n],       W[(k0 + 1) * N + n], h0, l0);
        pack_hl(W[(k0 + 8) * N + n], W[(k0 + 9) * N + n], h1, l1);
        frag[idx] = make_uint4(h0, h1, l0, l1);
    }
}

// One layer over two m16 tiles: each B load feeds 6 mma (3-term x 2 tiles).
template <int KS, int NF>
__device__ __forceinline__ void layer_mma2(float (&d0)[NF][4], float (&d1)[NF][4],
                                           const uint4* __restrict__ frag,
                                           const uint32_t (&A0h)[KS * 4], const uint32_t (&A0l)[KS * 4],
                                           const uint32_t (&A1h)[KS * 4], const uint32_t (&A1l)[KS * 4],
                                           int lane) {
#pragma unroll
    for (int j = 0; j < NF; j++) {
#pragma unroll
        for (int ks = 0; ks < KS; ks++) {
            uint4 b = frag[(ks * NF + j) * 32 + lane];
            mma16816(d0[j], &A0h[ks * 4], b.x, b.y);
            mma16816(d0[j], &A0l[ks * 4], b.x, b.y);
            mma16816(d0[j], &A0h[ks * 4], b.z, b.w);
            mma16816(d1[j], &A1h[ks * 4], b.x, b.y);
            mma16816(d1[j], &A1l[ks * 4], b.x, b.y);
            mma16816(d1[j], &A1h[ks * 4], b.z, b.w);
        }
    }
}

// Epilogue: D(8 n-tiles) + bias -> relu -> hi/lo A frags (4 ksteps).
__device__ __forceinline__ void epi_relu(const float (&d)[8][4],
                                         const float* __restrict__ bias, int lane,
                                         uint32_t (&Ah)[16], uint32_t (&Al)[16]) {
    int t = lane & 3;
#pragma unroll
    for (int ks = 0; ks < 4; ks++) {
#pragma unroll
        for (int h = 0; h < 2; h++) {
            int j = 2 * ks + h;
            float2 b = *(const float2*)&bias[j * 8 + 2 * t];
            float f0 = fmaxf(d[j][0] + b.x, 0.0f);
            float f1 = fmaxf(d[j][1] + b.y, 0.0f);
            float f2 = fmaxf(d[j][2] + b.x, 0.0f);
            float f3 = fmaxf(d[j][3] + b.y, 0.0f);
            pack_hl(f0, f1, Ah[ks * 4 + h * 2 + 0], Al[ks * 4 + h * 2 + 0]);
            pack_hl(f2, f3, Ah[ks * 4 + h * 2 + 1], Al[ks * 4 + h * 2 + 1]);
        }
    }
}

__device__ __forceinline__ void load_x(const float* __restrict__ x, size_t rowbase,
                                       int g, int t, uint32_t (&Xh)[8], uint32_t (&Xl)[8]) {
    const float* xr0 = x + (rowbase + g) * 32;
    const float* xr8 = x + (rowbase + g + 8) * 32;
#pragma unroll
    for (int ks = 0; ks < 2; ks++) {
        float2 v0 = *(const float2*)&xr0[ks * 16 + 2 * t];
        float2 v1 = *(const float2*)&xr8[ks * 16 + 2 * t];
        float2 v2 = *(const float2*)&xr0[ks * 16 + 8 + 2 * t];
        float2 v3 = *(const float2*)&xr8[ks * 16 + 8 + 2 * t];
        pack_hl(v0.x, v0.y, Xh[ks * 4 + 0], Xl[ks * 4 + 0]);
        pack_hl(v1.x, v1.y, Xh[ks * 4 + 1], Xl[ks * 4 + 1]);
        pack_hl(v2.x, v2.y, Xh[ks * 4 + 2], Xl[ks * 4 + 2]);
        pack_hl(v3.x, v3.y, Xh[ks * 4 + 3], Xl[ks * 4 + 3]);
    }
}

__global__ void __launch_bounds__(THREADS, 3)
mlp_hmma_kernel(const float* __restrict__ x,
                const float* __restrict__ Wi, const float* __restrict__ bi,
                const float* __restrict__ W1, const float* __restrict__ b1,
                const float* __restrict__ W2, const float* __restrict__ b2,
                const float* __restrict__ Wo, const float* __restrict__ bo,
                float* __restrict__ out) {
    const int tid = threadIdx.x;
    const int wid = tid >> 5;
    const int lane = tid & 31;
    const int g = lane >> 2, t = lane & 3;

    stage(Wi, 32, 64, sf1, tid);
    stage(W1, 64, 64, sf2, tid);
    stage(W2, 64, 64, sf3, tid);
    stage(Wo, 64, 16, sf4, tid);
    for (int i = tid; i < 64; i += THREADS) { sb1[i] = bi[i]; sb2[i] = b1[i]; sb3[i] = b2[i]; }
    if (tid < 16) sb4[tid] = bo[tid];
    __syncthreads();

    const int wstride = gridDim.x * WARPS;
    for (int wt = blockIdx.x * WARPS + wid; wt < WTILES; wt += wstride) {
        const size_t rowbase = (size_t)wt * 32;

        // ---- A0/A1 from x (two 16-row tiles) ----
        uint32_t A0h[16], A0l[16], A1h[16], A1l[16];
        {
            uint32_t Xh[8], Xl[8];
            load_x(x, rowbase, g, t, Xh, Xl);
#pragma unroll
            for (int i = 0; i < 8; i++) { A0h[i] = Xh[i]; A0l[i] = Xl[i]; }
            load_x(x, rowbase + 16, g, t, Xh, Xl);
#pragma unroll
            for (int i = 0; i < 8; i++) { A1h[i] = Xh[i]; A1l[i] = Xl[i]; }
        }

        float d0[8][4], d1[8][4];

        // ---- L1: 32 -> 64 ----
#pragma unroll
        for (int j = 0; j < 8; j++)
#pragma unroll
            for (int e = 0; e < 4; e++) { d0[j][e] = 0.0f; d1[j][e] = 0.0f; }
        layer_mma2<2, 8>(d0, d1, sf1,
                         *(const uint32_t(*)[8])A0h, *(const uint32_t(*)[8])A0l,
                         *(const uint32_t(*)[8])A1h, *(const uint32_t(*)[8])A1l, lane);
        epi_relu(d0, sb1, lane, A0h, A0l);
        epi_relu(d1, sb1, lane, A1h, A1l);

        // ---- L2: 64 -> 64 ----
#pragma unroll
        for (int j = 0; j < 8; j++)
#pragma unroll
            for (int e = 0; e < 4; e++) { d0[j][e] = 0.0f; d1[j][e] = 0.0f; }
        layer_mma2<4, 8>(d0, d1, sf2, A0h, A0l, A1h, A1l, lane);
        epi_relu(d0, sb2, lane, A0h, A0l);
        epi_relu(d1, sb2, lane, A1h, A1l);

        // ---- L3: 64 -> 64 ----
#pragma unroll
        for (int j = 0; j < 8; j++)
#pragma unroll
            for (int e = 0; e < 4; e++) { d0[j][e] = 0.0f; d1[j][e] = 0.0f; }
        layer_mma2<4, 8>(d0, d1, sf3, A0h, A0l, A1h, A1l, lane);
        epi_relu(d0, sb3, lane, A0h, A0l);
        epi_relu(d1, sb3, lane, A1h, A1l);

        // ---- L4: 64 -> 16 ----
        float e0[2][4], e1[2][4];
#pragma unroll
        for (int j = 0; j < 2; j++)
#pragma unroll
            for (int e = 0; e < 4; e++) { e0[j][e] = 0.0f; e1[j][e] = 0.0f; }
        layer_mma2<4, 2>(e0, e1, sf4, A0h, A0l, A1h, A1l, lane);

        // ---- store both tiles ----
#pragma unroll
        for (int mt = 0; mt < 2; mt++) {
            const float (&dd)[2][4] = mt ? e1 : e0;
            float* o0 = out + (rowbase + mt * 16 + g) * 16;
            float* o8 = out + (rowbase + mt * 16 + g + 8) * 16;
#pragma unroll
            for (int j = 0; j < 2; j++) {
                float2 b = *(const float2*)&sb4[j * 8 + 2 * t];
                *(float2*)&o0[j * 8 + 2 * t] = make_float2(dd[j][0] + b.x, dd[j][1] + b.y);
                *(float2*)&o8[j * 8 + 2 * t] = make_float2(dd[j][2] + b.x, dd[j][3] + b.y);
            }
        }
    }
}

extern "C" void kernel_launch(void* const* d_in, const int* in_sizes, int n_in,
                              void* d_out, int out_size) {
    (void)in_sizes; (void)n_in; (void)out_size;
    const float* x  = (const float*)d_in[0];
    const float* Wi = (const float*)d_in[1];
    const float* bi = (const float*)d_in[2];
    const float* W1 = (const float*)d_in[3];
    const float* b1 = (const float*)d_in[4];
    const float* W2 = (const float*)d_in[5];
    const float* b2 = (const float*)d_in[6];
    const float* Wo = (const float*)d_in[7];
    const float* bo = (const float*)d_in[8];
    float* out = (float*)d_out;

    mlp_hmma_kernel<<<GRID, THREADS>>>(x, Wi, bi, W1, b1, W2, b2, Wo, bo, out);
}

// round 7
// speedup vs baseline: 1.0033x; 1.0033x over previous
#include <cuda_runtime.h>
#include <cuda_fp16.h>
#include <cstdint>

// InstantNGPMLP fused on mma.sync m16n8k16 (tcgen05 unavailable under the
// harness's compute_103 virtual arch).
// R7 vs R5 (197us, tensor=58.8%, occ=20.4%) / R6 (203us, M=32 reg-bound):
//   - weight fragments moved smem -> __device__ global (L2-hot, LDG.128
//     broadcast); smem now ~1KB -> occupancy register-bound
//   - prep kernel builds fragments once; main kernel launch_bounds(128,5)
//     -> 5 CTAs/SM, 20 warps (was 13)
//   - compute structure identical to R5 (M=16/warp, 3-term hi/lo fp16 split)

#define THREADS 128
#define WARPS 4
#define NROWS 1048576
#define WTILES (NROWS / 16)   // 65536 warp-tiles of 16 rows
#define GRID 740              // 5 CTAs/SM * 148

// ---- global fragment storage (interleaved {bh0,bh1,bl0,bl1}) ----
__device__ uint4 g_f1[512];    // L1: 2ks x 8nf x 32 lanes
__device__ uint4 g_f2[1024];   // L2: 4ks x 8nf x 32
__device__ uint4 g_f3[1024];   // L3
__device__ uint4 g_f4[256];    // L4: 4ks x 2nf x 32

__device__ __forceinline__ void mma16816(float d[4], const uint32_t* a, uint32_t b0, uint32_t b1) {
    asm volatile(
        "mma.sync.aligned.m16n8k16.row.col.f32.f16.f16.f32 "
        "{%0,%1,%2,%3}, {%4,%5,%6,%7}, {%8,%9}, {%0,%1,%2,%3};"
        : "+f"(d[0]), "+f"(d[1]), "+f"(d[2]), "+f"(d[3])
        : "r"(a[0]), "r"(a[1]), "r"(a[2]), "r"(a[3]), "r"(b0), "r"(b1));
}

__device__ __forceinline__ void pack_hl(float f0, float f1, uint32_t& hi, uint32_t& lo) {
    __half h0 = __float2half_rn(f0);
    __half h1 = __float2half_rn(f1);
    __half l0 = __float2half_rn(f0 - __half2float(h0));
    __half l1 = __float2half_rn(f1 - __half2float(h1));
    hi = (uint32_t)__half_as_ushort(h0) | ((uint32_t)__half_as_ushort(h1) << 16);
    lo = (uint32_t)__half_as_ushort(l0) | ((uint32_t)__half_as_ushort(l1) << 16);
}

// ---- prep kernel: build B fragments in global (runs once, before main) ----
__device__ void stage_g(const float* __restrict__ W, int K, int N,
                        uint4* __restrict__ frag, int tid, int nthr) {
    const int NF = N / 8, total = (K / 16) * NF * 32;
    for (int idx = tid; idx < total; idx += nthr) {
        int lane = idx & 31, f = idx >> 5;
        int j = f % NF, ks = f / NF;
        int g = lane >> 2, t = lane & 3;
        int n = j * 8 + g;
        int k0 = ks * 16 + 2 * t;
        uint32_t h0, l0, h1, l1;
        pack_hl(W[k0 * N + n],       W[(k0 + 1) * N + n], h0, l0);
        pack_hl(W[(k0 + 8) * N + n], W[(k0 + 9) * N + n], h1, l1);
        frag[idx] = make_uint4(h0, h1, l0, l1);
    }
}

__global__ void prep_kernel(const float* __restrict__ Wi, const float* __restrict__ W1,
                            const float* __restrict__ W2, const float* __restrict__ Wo) {
    int tid = threadIdx.x;
    stage_g(Wi, 32, 64, g_f1, tid, 256);
    stage_g(W1, 64, 64, g_f2, tid, 256);
    stage_g(W2, 64, 64, g_f3, tid, 256);
    stage_g(Wo, 64, 16, g_f4, tid, 256);
}

// ---- main kernel ----
__shared__ float sb1[64], sb2[64], sb3[64], sb4[16];

template <int KS, int NF>
__device__ __forceinline__ void layer_mma(float (&d)[NF][4],
                                          const uint4* __restrict__ frag,
                                          const uint32_t (&Ah)[KS * 4],
                                          const uint32_t (&Al)[KS * 4], int lane) {
#pragma unroll
    for (int j = 0; j < NF; j++) {
#pragma unroll
        for (int ks = 0; ks < KS; ks++) {
            uint4 b = __ldg(&frag[(ks * NF + j) * 32 + lane]);
            mma16816(d[j], &Ah[ks * 4], b.x, b.y);
            mma16816(d[j], &Al[ks * 4], b.x, b.y);
            mma16816(d[j], &Ah[ks * 4], b.z, b.w);
        }
    }
}

__device__ __forceinline__ void epi_relu(const float (&d)[8][4],
                                         const float* __restrict__ bias, int lane,
                                         uint32_t (&Ah)[16], uint32_t (&Al)[16]) {
    int t = lane & 3;
#pragma unroll
    for (int ks = 0; ks < 4; ks++) {
#pragma unroll
        for (int h = 0; h < 2; h++) {
            int j = 2 * ks + h;
            float2 b = *(const float2*)&bias[j * 8 + 2 * t];
            float f0 = fmaxf(d[j][0] + b.x, 0.0f);
            float f1 = fmaxf(d[j][1] + b.y, 0.0f);
            float f2 = fmaxf(d[j][2] + b.x, 0.0f);
            float f3 = fmaxf(d[j][3] + b.y, 0.0f);
            pack_hl(f0, f1, Ah[ks * 4 + h * 2 + 0], Al[ks * 4 + h * 2 + 0]);
            pack_hl(f2, f3, Ah[ks * 4 + h * 2 + 1], Al[ks * 4 + h * 2 + 1]);
        }
    }
}

__global__ void __launch_bounds__(THREADS, 5)
mlp_hmma_kernel(const float* __restrict__ x,
                const float* __restrict__ bi, const float* __restrict__ b1,
                const float* __restrict__ b2, const float* __restrict__ bo,
                float* __restrict__ out) {
    const int tid = threadIdx.x;
    const int wid = tid >> 5;
    const int lane = tid & 31;
    const int g = lane >> 2, t = lane & 3;

    for (int i = tid; i < 64; i += THREADS) { sb1[i] = bi[i]; sb2[i] = b1[i]; sb3[i] = b2[i]; }
    if (tid < 16) sb4[tid] = bo[tid];
    __syncthreads();

    const int wstride = gridDim.x * WARPS;
    for (int wt = blockIdx.x * WARPS + wid; wt < WTILES; wt += wstride) {
        const size_t rowbase = (size_t)wt * 16;

        // ---- load x (16x32) as hi/lo A fragments (2 ksteps) ----
        uint32_t Ah[16], Al[16];
        {
            const float* xr0 = x + (rowbase + g) * 32;
            const float* xr8 = x + (rowbase + g + 8) * 32;
#pragma unroll
            for (int ks = 0; ks < 2; ks++) {
                float2 v0 = *(const float2*)&xr0[ks * 16 + 2 * t];
                float2 v1 = *(const float2*)&xr8[ks * 16 + 2 * t];
                float2 v2 = *(const float2*)&xr0[ks * 16 + 8 + 2 * t];
                float2 v3 = *(const float2*)&xr8[ks * 16 + 8 + 2 * t];
                pack_hl(v0.x, v0.y, Ah[ks * 4 + 0], Al[ks * 4 + 0]);
                pack_hl(v1.x, v1.y, Ah[ks * 4 + 1], Al[ks * 4 + 1]);
                pack_hl(v2.x, v2.y, Ah[ks * 4 + 2], Al[ks * 4 + 2]);
                pack_hl(v3.x, v3.y, Ah[ks * 4 + 3], Al[ks * 4 + 3]);
            }
        }

        float d[8][4];

        // ---- L1: 32 -> 64 (uses only Ah/Al[0..7]) ----
#pragma unroll
        for (int j = 0; j < 8; j++)
#pragma unroll
            for (int e = 0; e < 4; e++) d[j][e] = 0.0f;
        layer_mma<2, 8>(d, g_f1, *(const uint32_t(*)[8])Ah, *(const uint32_t(*)[8])Al, lane);
        epi_relu(d, sb1, lane, Ah, Al);

        // ---- L2: 64 -> 64 ----
#pragma unroll
        for (int j = 0; j < 8; j++)
#pragma unroll
            for (int e = 0; e < 4; e++) d[j][e] = 0.0f;
        layer_mma<4, 8>(d, g_f2, Ah, Al, lane);
        epi_relu(d, sb2, lane, Ah, Al);

        // ---- L3: 64 -> 64 ----
#pragma unroll
        for (int j = 0; j < 8; j++)
#pragma unroll
            for (int e = 0; e < 4; e++) d[j][e] = 0.0f;
        layer_mma<4, 8>(d, g_f3, Ah, Al, lane);
        epi_relu(d, sb3, lane, Ah, Al);

        // ---- L4: 64 -> 16 (no relu) ----
        float d4[2][4];
#pragma unroll
        for (int j = 0; j < 2; j++)
#pragma unroll
            for (int e = 0; e < 4; e++) d4[j][e] = 0.0f;
        layer_mma<4, 2>(d4, g_f4, Ah, Al, lane);

        // ---- store: rows g, g+8; cols 8j+2t, +1 ----
        {
            float* o0 = out + (rowbase + g) * 16;
            float* o8 = out + (rowbase + g + 8) * 16;
#pragma unroll
            for (int j = 0; j < 2; j++) {
                float2 b = *(const float2*)&sb4[j * 8 + 2 * t];
                *(float2*)&o0[j * 8 + 2 * t] = make_float2(d4[j][0] + b.x, d4[j][1] + b.y);
                *(float2*)&o8[j * 8 + 2 * t] = make_float2(d4[j][2] + b.x, d4[j][3] + b.y);
            }
        }
    }
}

extern "C" void kernel_launch(void* const* d_in, const int* in_sizes, int n_in,
                              void* d_out, int out_size) {
    (void)in_sizes; (void)n_in; (void)out_size;
    const float* x  = (const float*)d_in[0];
    const float* Wi = (const float*)d_in[1];
    const float* bi = (const float*)d_in[2];
    const float* W1 = (const float*)d_in[3];
    const float* b1 = (const float*)d_in[4];
    const float* W2 = (const float*)d_in[5];
    const float* b2 = (const float*)d_in[6];
    const float* Wo = (const float*)d_in[7];
    const float* bo = (const float*)d_in[8];
    float* out = (float*)d_out;

    prep_kernel<<<1, 256>>>(Wi, W1, W2, Wo);
    mlp_hmma_kernel<<<GRID, THREADS>>>(x, bi, b1, b2, bo, out);
}

// round 8
// speedup vs baseline: 1.0215x; 1.0181x over previous
#include <cuda_runtime.h>
#include <cuda_fp16.h>
#include <cstdint>

// InstantNGPMLP fused on mma.sync m16n8k16 (tcgen05 unavailable under the
// harness's compute_103 virtual arch).
// R8 vs R7 (195us, tensor=60.3%, occ=25.3%):
//   - KEY FIX: mma loop interchanged. Old: all 12 mmas of one accumulator
//     chain consecutive -> in-order issue stalls on HMMA latency (tensor
//     plateau at 60%). New: per k-step, load 8 B-frags, then sweep j for
//     each of the 3 split terms -> dependent mmas separated by 7 independent
//     ones -> tensor pipe saturates.
//   - launch_bounds(128,4) (live B-frags add ~32 regs), prep kernel 8 blocks.

#define THREADS 128
#define WARPS 4
#define NROWS 1048576
#define WTILES (NROWS / 16)   // 65536 warp-tiles of 16 rows
#define GRID 592              // 4 CTAs/SM * 148

// ---- global fragment storage (interleaved {bh0,bh1,bl0,bl1}) ----
__device__ uint4 g_f1[512];    // L1: 2ks x 8nf x 32 lanes
__device__ uint4 g_f2[1024];   // L2: 4ks x 8nf x 32
__device__ uint4 g_f3[1024];   // L3
__device__ uint4 g_f4[256];    // L4: 4ks x 2nf x 32

__device__ __forceinline__ void mma16816(float d[4], const uint32_t* a, uint32_t b0, uint32_t b1) {
    asm volatile(
        "mma.sync.aligned.m16n8k16.row.col.f32.f16.f16.f32 "
        "{%0,%1,%2,%3}, {%4,%5,%6,%7}, {%8,%9}, {%0,%1,%2,%3};"
        : "+f"(d[0]), "+f"(d[1]), "+f"(d[2]), "+f"(d[3])
        : "r"(a[0]), "r"(a[1]), "r"(a[2]), "r"(a[3]), "r"(b0), "r"(b1));
}

__device__ __forceinline__ void pack_hl(float f0, float f1, uint32_t& hi, uint32_t& lo) {
    __half h0 = __float2half_rn(f0);
    __half h1 = __float2half_rn(f1);
    __half l0 = __float2half_rn(f0 - __half2float(h0));
    __half l1 = __float2half_rn(f1 - __half2float(h1));
    hi = (uint32_t)__half_as_ushort(h0) | ((uint32_t)__half_as_ushort(h1) << 16);
    lo = (uint32_t)__half_as_ushort(l0) | ((uint32_t)__half_as_ushort(l1) << 16);
}

// ---- prep kernel: build B fragments in global (runs once, before main) ----
__device__ void stage_g(const float* __restrict__ W, int K, int N,
                        uint4* __restrict__ frag, int tid, int nthr) {
    const int NF = N / 8, total = (K / 16) * NF * 32;
    for (int idx = tid; idx < total; idx += nthr) {
        int lane = idx & 31, f = idx >> 5;
        int j = f % NF, ks = f / NF;
        int g = lane >> 2, t = lane & 3;
        int n = j * 8 + g;
        int k0 = ks * 16 + 2 * t;
        uint32_t h0, l0, h1, l1;
        pack_hl(W[k0 * N + n],       W[(k0 + 1) * N + n], h0, l0);
        pack_hl(W[(k0 + 8) * N + n], W[(k0 + 9) * N + n], h1, l1);
        frag[idx] = make_uint4(h0, h1, l0, l1);
    }
}

__global__ void prep_kernel(const float* __restrict__ Wi, const float* __restrict__ W1,
                            const float* __restrict__ W2, const float* __restrict__ Wo) {
    int tid = blockIdx.x * blockDim.x + threadIdx.x;
    int nthr = gridDim.x * blockDim.x;
    stage_g(Wi, 32, 64, g_f1, tid, nthr);
    stage_g(W1, 64, 64, g_f2, tid, nthr);
    stage_g(W2, 64, 64, g_f3, tid, nthr);
    stage_g(Wo, 64, 16, g_f4, tid, nthr);
}

// ---- main kernel ----
__shared__ float sb1[64], sb2[64], sb3[64], sb4[16];

// Interleaved-chain layer: per k-step load all NF B-frags, then issue each
// split term across all j (dependent mmas spaced NF apart in the stream).
template <int KS, int NF>
__device__ __forceinline__ void layer_mma(float (&d)[NF][4],
                                          const uint4* __restrict__ frag,
                                          const uint32_t (&Ah)[KS * 4],
                                          const uint32_t (&Al)[KS * 4], int lane) {
#pragma unroll
    for (int ks = 0; ks < KS; ks++) {
        uint4 b[NF];
#pragma unroll
        for (int j = 0; j < NF; j++) b[j] = __ldg(&frag[(ks * NF + j) * 32 + lane]);
#pragma unroll
        for (int j = 0; j < NF; j++) mma16816(d[j], &Ah[ks * 4], b[j].x, b[j].y);
#pragma unroll
        for (int j = 0; j < NF; j++) mma16816(d[j], &Al[ks * 4], b[j].x, b[j].y);
#pragma unroll
        for (int j = 0; j < NF; j++) mma16816(d[j], &Ah[ks * 4], b[j].z, b[j].w);
    }
}

__device__ __forceinline__ void epi_relu(const float (&d)[8][4],
                                         const float* __restrict__ bias, int lane,
                                         uint32_t (&Ah)[16], uint32_t (&Al)[16]) {
    int t = lane & 3;
#pragma unroll
    for (int ks = 0; ks < 4; ks++) {
#pragma unroll
        for (int h = 0; h < 2; h++) {
            int j = 2 * ks + h;
            float2 b = *(const float2*)&bias[j * 8 + 2 * t];
            float f0 = fmaxf(d[j][0] + b.x, 0.0f);
            float f1 = fmaxf(d[j][1] + b.y, 0.0f);
            float f2 = fmaxf(d[j][2] + b.x, 0.0f);
            float f3 = fmaxf(d[j][3] + b.y, 0.0f);
            pack_hl(f0, f1, Ah[ks * 4 + h * 2 + 0], Al[ks * 4 + h * 2 + 0]);
            pack_hl(f2, f3, Ah[ks * 4 + h * 2 + 1], Al[ks * 4 + h * 2 + 1]);
        }
    }
}

__global__ void __launch_bounds__(THREADS, 4)
mlp_hmma_kernel(const float* __restrict__ x,
                const float* __restrict__ bi, const float* __restrict__ b1,
                const float* __restrict__ b2, const float* __restrict__ bo,
                float* __restrict__ out) {
    const int tid = threadIdx.x;
    const int wid = tid >> 5;
    const int lane = tid & 31;
    const int g = lane >> 2, t = lane & 3;

    for (int i = tid; i < 64; i += THREADS) { sb1[i] = bi[i]; sb2[i] = b1[i]; sb3[i] = b2[i]; }
    if (tid < 16) sb4[tid] = bo[tid];
    __syncthreads();

    const int wstride = gridDim.x * WARPS;
    for (int wt = blockIdx.x * WARPS + wid; wt < WTILES; wt += wstride) {
        const size_t rowbase = (size_t)wt * 16;

        // ---- load x (16x32) as hi/lo A fragments (2 ksteps) ----
        uint32_t Ah[16], Al[16];
        {
            const float* xr0 = x + (rowbase + g) * 32;
            const float* xr8 = x + (rowbase + g + 8) * 32;
#pragma unroll
            for (int ks = 0; ks < 2; ks++) {
                float2 v0 = *(const float2*)&xr0[ks * 16 + 2 * t];
                float2 v1 = *(const float2*)&xr8[ks * 16 + 2 * t];
                float2 v2 = *(const float2*)&xr0[ks * 16 + 8 + 2 * t];
                float2 v3 = *(const float2*)&xr8[ks * 16 + 8 + 2 * t];
                pack_hl(v0.x, v0.y, Ah[ks * 4 + 0], Al[ks * 4 + 0]);
                pack_hl(v1.x, v1.y, Ah[ks * 4 + 1], Al[ks * 4 + 1]);
                pack_hl(v2.x, v2.y, Ah[ks * 4 + 2], Al[ks * 4 + 2]);
                pack_hl(v3.x, v3.y, Ah[ks * 4 + 3], Al[ks * 4 + 3]);
            }
        }

        float d[8][4];

        // ---- L1: 32 -> 64 (uses only Ah/Al[0..7]) ----
#pragma unroll
        for (int j = 0; j < 8; j++)
#pragma unroll
            for (int e = 0; e < 4; e++) d[j][e] = 0.0f;
        layer_mma<2, 8>(d, g_f1, *(const uint32_t(*)[8])Ah, *(const uint32_t(*)[8])Al, lane);
        epi_relu(d, sb1, lane, Ah, Al);

        // ---- L2: 64 -> 64 ----
#pragma unroll
        for (int j = 0; j < 8; j++)
#pragma unroll
            for (int e = 0; e < 4; e++) d[j][e] = 0.0f;
        layer_mma<4, 8>(d, g_f2, Ah, Al, lane);
        epi_relu(d, sb2, lane, Ah, Al);

        // ---- L3: 64 -> 64 ----
#pragma unroll
        for (int j = 0; j < 8; j++)
#pragma unroll
            for (int e = 0; e < 4; e++) d[j][e] = 0.0f;
        layer_mma<4, 8>(d, g_f3, Ah, Al, lane);
        epi_relu(d, sb3, lane, Ah, Al);

        // ---- L4: 64 -> 16 (no relu) ----
        float d4[2][4];
#pragma unroll
        for (int j = 0; j < 2; j++)
#pragma unroll
            for (int e = 0; e < 4; e++) d4[j][e] = 0.0f;
        layer_mma<4, 2>(d4, g_f4, Ah, Al, lane);

        // ---- store: rows g, g+8; cols 8j+2t, +1 ----
        {
            float* o0 = out + (rowbase + g) * 16;
            float* o8 = out + (rowbase + g + 8) * 16;
#pragma unroll
            for (int j = 0; j < 2; j++) {
                float2 b = *(const float2*)&sb4[j * 8 + 2 * t];
                *(float2*)&o0[j * 8 + 2 * t] = make_float2(d4[j][0] + b.x, d4[j][1] + b.y);
                *(float2*)&o8[j * 8 + 2 * t] = make_float2(d4[j][2] + b.x, d4[j][3] + b.y);
            }
        }
    }
}

extern "C" void kernel_launch(void* const* d_in, const int* in_sizes, int n_in,
                              void* d_out, int out_size) {
    (void)in_sizes; (void)n_in; (void)out_size;
    const float* x  = (const float*)d_in[0];
    const float* Wi = (const float*)d_in[1];
    const float* bi = (const float*)d_in[2];
    const float* W1 = (const float*)d_in[3];
    const float* b1 = (const float*)d_in[4];
    const float* W2 = (const float*)d_in[5];
    const float* b2 = (const float*)d_in[6];
    const float* Wo = (const float*)d_in[7];
    const float* bo = (const float*)d_in[8];
    float* out = (float*)d_out;

    prep_kernel<<<8, 256>>>(Wi, W1, W2, Wo);
    mlp_hmma_kernel<<<GRID, THREADS>>>(x, bi, b1, b2, bo, out);
}

// round 9
// speedup vs baseline: 1.1418x; 1.1178x over previous
#include <cuda_runtime.h>
#include <cuda_fp16.h>
#include <cstdint>

// InstantNGPMLP fused on mma.sync m16n8k16 (tcgen05 unavailable under the
// harness's compute_103 virtual arch).
// R9 vs R8 (199us, tensor=59.4% — invariant across 4 structures => fp32-accum
// HMMA pipe saturated):
//   - 2-term split: D = Ah*Bh + Al*Bh (weights fp16-rounded, activations
//     keep hi/lo split). mma/tile 264 -> 176 (-33%).
//   - B fragments shrink to uint2 (hi only): weight L1 traffic halved,
//     ~16 fewer live regs -> chain interleave no longer reg-starved.
//   - expected rel_err ~1-4e-4 (was 5.3e-7); revert to 3-term if > 7e-4.

#define THREADS 128
#define WARPS 4
#define NROWS 1048576
#define WTILES (NROWS / 16)   // 65536 warp-tiles of 16 rows
#define GRID 592              // 4 CTAs/SM * 148

// ---- global fragment storage ({bh0, bh1} per lane) ----
__device__ uint2 g_f1[512];    // L1: 2ks x 8nf x 32 lanes
__device__ uint2 g_f2[1024];   // L2: 4ks x 8nf x 32
__device__ uint2 g_f3[1024];   // L3
__device__ uint2 g_f4[256];    // L4: 4ks x 2nf x 32

__device__ __forceinline__ void mma16816(float d[4], const uint32_t* a, uint32_t b0, uint32_t b1) {
    asm volatile(
        "mma.sync.aligned.m16n8k16.row.col.f32.f16.f16.f32 "
        "{%0,%1,%2,%3}, {%4,%5,%6,%7}, {%8,%9}, {%0,%1,%2,%3};"
        : "+f"(d[0]), "+f"(d[1]), "+f"(d[2]), "+f"(d[3])
        : "r"(a[0]), "r"(a[1]), "r"(a[2]), "r"(a[3]), "r"(b0), "r"(b1));
}

__device__ __forceinline__ void pack_hl(float f0, float f1, uint32_t& hi, uint32_t& lo) {
    __half h0 = __float2half_rn(f0);
    __half h1 = __float2half_rn(f1);
    __half l0 = __float2half_rn(f0 - __half2float(h0));
    __half l1 = __float2half_rn(f1 - __half2float(h1));
    hi = (uint32_t)__half_as_ushort(h0) | ((uint32_t)__half_as_ushort(h1) << 16);
    lo = (uint32_t)__half_as_ushort(l0) | ((uint32_t)__half_as_ushort(l1) << 16);
}
__device__ __forceinline__ uint32_t pack_h(float f0, float f1) {
    __half h0 = __float2half_rn(f0);
    __half h1 = __float2half_rn(f1);
    return (uint32_t)__half_as_ushort(h0) | ((uint32_t)__half_as_ushort(h1) << 16);
}

// ---- prep kernel: build hi-only B fragments in global ----
__device__ void stage_g(const float* __restrict__ W, int K, int N,
                        uint2* __restrict__ frag, int tid, int nthr) {
    const int NF = N / 8, total = (K / 16) * NF * 32;
    for (int idx = tid; idx < total; idx += nthr) {
        int lane = idx & 31, f = idx >> 5;
        int j = f % NF, ks = f / NF;
        int g = lane >> 2, t = lane & 3;
        int n = j * 8 + g;
        int k0 = ks * 16 + 2 * t;
        frag[idx] = make_uint2(pack_h(W[k0 * N + n],       W[(k0 + 1) * N + n]),
                               pack_h(W[(k0 + 8) * N + n], W[(k0 + 9) * N + n]));
    }
}

__global__ void prep_kernel(const float* __restrict__ Wi, const float* __restrict__ W1,
                            const float* __restrict__ W2, const float* __restrict__ Wo) {
    int tid = blockIdx.x * blockDim.x + threadIdx.x;
    int nthr = gridDim.x * blockDim.x;
    stage_g(Wi, 32, 64, g_f1, tid, nthr);
    stage_g(W1, 64, 64, g_f2, tid, nthr);
    stage_g(W2, 64, 64, g_f3, tid, nthr);
    stage_g(Wo, 64, 16, g_f4, tid, nthr);
}

// ---- main kernel ----
__shared__ float sb1[64], sb2[64], sb3[64], sb4[16];

// 2-term interleaved-chain layer: per k-step load NF hi-frags, sweep j for
// Ah term then Al term (dependent mmas spaced NF apart).
template <int KS, int NF>
__device__ __forceinline__ void layer_mma(float (&d)[NF][4],
                                          const uint2* __restrict__ frag,
                                          const uint32_t (&Ah)[KS * 4],
                                          const uint32_t (&Al)[KS * 4], int lane) {
#pragma unroll
    for (int ks = 0; ks < KS; ks++) {
        uint2 b[NF];
#pragma unroll
        for (int j = 0; j < NF; j++) b[j] = __ldg(&frag[(ks * NF + j) * 32 + lane]);
#pragma unroll
        for (int j = 0; j < NF; j++) mma16816(d[j], &Ah[ks * 4], b[j].x, b[j].y);
#pragma unroll
        for (int j = 0; j < NF; j++) mma16816(d[j], &Al[ks * 4], b[j].x, b[j].y);
    }
}

__device__ __forceinline__ void epi_relu(const float (&d)[8][4],
                                         const float* __restrict__ bias, int lane,
                                         uint32_t (&Ah)[16], uint32_t (&Al)[16]) {
    int t = lane & 3;
#pragma unroll
    for (int ks = 0; ks < 4; ks++) {
#pragma unroll
        for (int h = 0; h < 2; h++) {
            int j = 2 * ks + h;
            float2 b = *(const float2*)&bias[j * 8 + 2 * t];
            float f0 = fmaxf(d[j][0] + b.x, 0.0f);
            float f1 = fmaxf(d[j][1] + b.y, 0.0f);
            float f2 = fmaxf(d[j][2] + b.x, 0.0f);
            float f3 = fmaxf(d[j][3] + b.y, 0.0f);
            pack_hl(f0, f1, Ah[ks * 4 + h * 2 + 0], Al[ks * 4 + h * 2 + 0]);
            pack_hl(f2, f3, Ah[ks * 4 + h * 2 + 1], Al[ks * 4 + h * 2 + 1]);
        }
    }
}

__global__ void __launch_bounds__(THREADS, 4)
mlp_hmma_kernel(const float* __restrict__ x,
                const float* __restrict__ bi, const float* __restrict__ b1,
                const float* __restrict__ b2, const float* __restrict__ bo,
                float* __restrict__ out) {
    const int tid = threadIdx.x;
    const int wid = tid >> 5;
    const int lane = tid & 31;
    const int g = lane >> 2, t = lane & 3;

    for (int i = tid; i < 64; i += THREADS) { sb1[i] = bi[i]; sb2[i] = b1[i]; sb3[i] = b2[i]; }
    if (tid < 16) sb4[tid] = bo[tid];
    __syncthreads();

    const int wstride = gridDim.x * WARPS;
    for (int wt = blockIdx.x * WARPS + wid; wt < WTILES; wt += wstride) {
        const size_t rowbase = (size_t)wt * 16;

        // ---- load x (16x32) as hi/lo A fragments (2 ksteps) ----
        uint32_t Ah[16], Al[16];
        {
            const float* xr0 = x + (rowbase + g) * 32;
            const float* xr8 = x + (rowbase + g + 8) * 32;
#pragma unroll
            for (int ks = 0; ks < 2; ks++) {
                float2 v0 = *(const float2*)&xr0[ks * 16 + 2 * t];
                float2 v1 = *(const float2*)&xr8[ks * 16 + 2 * t];
                float2 v2 = *(const float2*)&xr0[ks * 16 + 8 + 2 * t];
                float2 v3 = *(const float2*)&xr8[ks * 16 + 8 + 2 * t];
                pack_hl(v0.x, v0.y, Ah[ks * 4 + 0], Al[ks * 4 + 0]);
                pack_hl(v1.x, v1.y, Ah[ks * 4 + 1], Al[ks * 4 + 1]);
                pack_hl(v2.x, v2.y, Ah[ks * 4 + 2], Al[ks * 4 + 2]);
                pack_hl(v3.x, v3.y, Ah[ks * 4 + 3], Al[ks * 4 + 3]);
            }
        }

        float d[8][4];

        // ---- L1: 32 -> 64 ----
#pragma unroll
        for (int j = 0; j < 8; j++)
#pragma unroll
            for (int e = 0; e < 4; e++) d[j][e] = 0.0f;
        layer_mma<2, 8>(d, g_f1, *(const uint32_t(*)[8])Ah, *(const uint32_t(*)[8])Al, lane);
        epi_relu(d, sb1, lane, Ah, Al);

        // ---- L2: 64 -> 64 ----
#pragma unroll
        for (int j = 0; j < 8; j++)
#pragma unroll
            for (int e = 0; e < 4; e++) d[j][e] = 0.0f;
        layer_mma<4, 8>(d, g_f2, Ah, Al, lane);
        epi_relu(d, sb2, lane, Ah, Al);

        // ---- L3: 64 -> 64 ----
#pragma unroll
        for (int j = 0; j < 8; j++)
#pragma unroll
            for (int e = 0; e < 4; e++) d[j][e] = 0.0f;
        layer_mma<4, 8>(d, g_f3, Ah, Al, lane);
        epi_relu(d, sb3, lane, Ah, Al);

        // ---- L4: 64 -> 16 (no relu) ----
        float d4[2][4];
#pragma unroll
        for (int j = 0; j < 2; j++)
#pragma unroll
            for (int e = 0; e < 4; e++) d4[j][e] = 0.0f;
        layer_mma<4, 2>(d4, g_f4, Ah, Al, lane);

        // ---- store: rows g, g+8; cols 8j+2t, +1 ----
        {
            float* o0 = out + (rowbase + g) * 16;
            float* o8 = out + (rowbase + g + 8) * 16;
#pragma unroll
            for (int j = 0; j < 2; j++) {
                float2 b = *(const float2*)&sb4[j * 8 + 2 * t];
                *(float2*)&o0[j * 8 + 2 * t] = make_float2(d4[j][0] + b.x, d4[j][1] + b.y);
                *(float2*)&o8[j * 8 + 2 * t] = make_float2(d4[j][2] + b.x, d4[j][3] + b.y);
            }
        }
    }
}

extern "C" void kernel_launch(void* const* d_in, const int* in_sizes, int n_in,
                              void* d_out, int out_size) {
    (void)in_sizes; (void)n_in; (void)out_size;
    const float* x  = (const float*)d_in[0];
    const float* Wi = (const float*)d_in[1];
    const float* bi = (const float*)d_in[2];
    const float* W1 = (const float*)d_in[3];
    const float* b1 = (const float*)d_in[4];
    const float* W2 = (const float*)d_in[5];
    const float* b2 = (const float*)d_in[6];
    const float* Wo = (const float*)d_in[7];
    const float* bo = (const float*)d_in[8];
    float* out = (float*)d_out;

    prep_kernel<<<8, 256>>>(Wi, W1, W2, Wo);
    mlp_hmma_kernel<<<GRID, THREADS>>>(x, bi, b1, b2, bo, out);
}

// round 10
// speedup vs baseline: 1.3389x; 1.1726x over previous
#include <cuda_runtime.h>
#include <cuda_fp16.h>
#include <cstdint>

// InstantNGPMLP fused on mma.sync m16n8k16 (tcgen05 unavailable under the
// harness's compute_103 virtual arch).
// R10 vs R9 (178us, tensor=44.7%, issue=38.5% -> LATENCY-bound, not pipe-bound):
//   - B fragments (2-term, hi-only, 22KB) back in smem: operand latency
//     234-262cyc (LDG/L2) -> 29cyc (LDS), conflict-free uint2 broadcast.
//   - x loads software-pipelined across tiles: next tile's raw LDGs issued
//     before current tile's mma work -> DRAM latency off the critical path.
//   - keep 2-term split (rel_err 2.0e-4, confirmed), 4 CTAs/SM.

#define THREADS 128
#define WARPS 4
#define NROWS 1048576
#define WTILES (NROWS / 16)   // 65536 warp-tiles of 16 rows
#define GRID 592              // 4 CTAs/SM * 148

__device__ __forceinline__ void mma16816(float d[4], const uint32_t* a, uint32_t b0, uint32_t b1) {
    asm volatile(
        "mma.sync.aligned.m16n8k16.row.col.f32.f16.f16.f32 "
        "{%0,%1,%2,%3}, {%4,%5,%6,%7}, {%8,%9}, {%0,%1,%2,%3};"
        : "+f"(d[0]), "+f"(d[1]), "+f"(d[2]), "+f"(d[3])
        : "r"(a[0]), "r"(a[1]), "r"(a[2]), "r"(a[3]), "r"(b0), "r"(b1));
}

__device__ __forceinline__ void pack_hl(float f0, float f1, uint32_t& hi, uint32_t& lo) {
    __half h0 = __float2half_rn(f0);
    __half h1 = __float2half_rn(f1);
    __half l0 = __float2half_rn(f0 - __half2float(h0));
    __half l1 = __float2half_rn(f1 - __half2float(h1));
    hi = (uint32_t)__half_as_ushort(h0) | ((uint32_t)__half_as_ushort(h1) << 16);
    lo = (uint32_t)__half_as_ushort(l0) | ((uint32_t)__half_as_ushort(l1) << 16);
}
__device__ __forceinline__ uint32_t pack_h(float f0, float f1) {
    __half h0 = __float2half_rn(f0);
    __half h1 = __float2half_rn(f1);
    return (uint32_t)__half_as_ushort(h0) | ((uint32_t)__half_as_ushort(h1) << 16);
}

// ---- smem: hi-only B fragments (~22KB) + biases ----
__shared__ uint2 sf1[512];    // L1: 2ks x 8nf x 32 lanes
__shared__ uint2 sf2[1024];   // L2: 4ks x 8nf x 32
__shared__ uint2 sf3[1024];   // L3
__shared__ uint2 sf4[256];    // L4: 4ks x 2nf x 32
__shared__ float sb1[64], sb2[64], sb3[64], sb4[16];

__device__ void stage(const float* __restrict__ W, int K, int N,
                      uint2* __restrict__ frag, int tid) {
    const int NF = N / 8, total = (K / 16) * NF * 32;
    for (int idx = tid; idx < total; idx += THREADS) {
        int lane = idx & 31, f = idx >> 5;
        int j = f % NF, ks = f / NF;
        int g = lane >> 2, t = lane & 3;
        int n = j * 8 + g;
        int k0 = ks * 16 + 2 * t;
        frag[idx] = make_uint2(pack_h(W[k0 * N + n],       W[(k0 + 1) * N + n]),
                               pack_h(W[(k0 + 8) * N + n], W[(k0 + 9) * N + n]));
    }
}

// 2-term interleaved-chain layer: per k-step load NF hi-frags (LDS), sweep j
// for Ah term then Al term (dependent mmas spaced NF apart).
template <int KS, int NF>
__device__ __forceinline__ void layer_mma(float (&d)[NF][4],
                                          const uint2* __restrict__ frag,
                                          const uint32_t (&Ah)[KS * 4],
                                          const uint32_t (&Al)[KS * 4], int lane) {
#pragma unroll
    for (int ks = 0; ks < KS; ks++) {
        uint2 b[NF];
#pragma unroll
        for (int j = 0; j < NF; j++) b[j] = frag[(ks * NF + j) * 32 + lane];
#pragma unroll
        for (int j = 0; j < NF; j++) mma16816(d[j], &Ah[ks * 4], b[j].x, b[j].y);
#pragma unroll
        for (int j = 0; j < NF; j++) mma16816(d[j], &Al[ks * 4], b[j].x, b[j].y);
    }
}

__device__ __forceinline__ void epi_relu(const float (&d)[8][4],
                                         const float* __restrict__ bias, int lane,
                                         uint32_t (&Ah)[16], uint32_t (&Al)[16]) {
    int t = lane & 3;
#pragma unroll
    for (int ks = 0; ks < 4; ks++) {
#pragma unroll
        for (int h = 0; h < 2; h++) {
            int j = 2 * ks + h;
            float2 b = *(const float2*)&bias[j * 8 + 2 * t];
            float f0 = fmaxf(d[j][0] + b.x, 0.0f);
            float f1 = fmaxf(d[j][1] + b.y, 0.0f);
            float f2 = fmaxf(d[j][2] + b.x, 0.0f);
            float f3 = fmaxf(d[j][3] + b.y, 0.0f);
            pack_hl(f0, f1, Ah[ks * 4 + h * 2 + 0], Al[ks * 4 + h * 2 + 0]);
            pack_hl(f2, f3, Ah[ks * 4 + h * 2 + 1], Al[ks * 4 + h * 2 + 1]);
        }
    }
}

// Raw x loads for one 16-row tile (8 float2 per thread), no conversion.
__device__ __forceinline__ void load_raw(const float* __restrict__ x, size_t rowbase,
                                         int g, int t, float2 (&raw)[8]) {
    const float* xr0 = x + (rowbase + g) * 32;
    const float* xr8 = x + (rowbase + g + 8) * 32;
#pragma unroll
    for (int ks = 0; ks < 2; ks++) {
        raw[ks * 4 + 0] = *(const float2*)&xr0[ks * 16 + 2 * t];
        raw[ks * 4 + 1] = *(const float2*)&xr8[ks * 16 + 2 * t];
        raw[ks * 4 + 2] = *(const float2*)&xr0[ks * 16 + 8 + 2 * t];
        raw[ks * 4 + 3] = *(const float2*)&xr8[ks * 16 + 8 + 2 * t];
    }
}

__global__ void __launch_bounds__(THREADS, 4)
mlp_hmma_kernel(const float* __restrict__ x,
                const float* __restrict__ Wi, const float* __restrict__ bi,
                const float* __restrict__ W1, const float* __restrict__ b1,
                const float* __restrict__ W2, const float* __restrict__ b2,
                const float* __restrict__ Wo, const float* __restrict__ bo,
                float* __restrict__ out) {
    const int tid = threadIdx.x;
    const int wid = tid >> 5;
    const int lane = tid & 31;
    const int g = lane >> 2, t = lane & 3;

    stage(Wi, 32, 64, sf1, tid);
    stage(W1, 64, 64, sf2, tid);
    stage(W2, 64, 64, sf3, tid);
    stage(Wo, 64, 16, sf4, tid);
    for (int i = tid; i < 64; i += THREADS) { sb1[i] = bi[i]; sb2[i] = b1[i]; sb3[i] = b2[i]; }
    if (tid < 16) sb4[tid] = bo[tid];
    __syncthreads();

    const int wstride = gridDim.x * WARPS;
    int wt = blockIdx.x * WARPS + wid;

    // ---- prologue: raw x loads for first tile ----
    float2 raw[8];
    if (wt < WTILES) load_raw(x, (size_t)wt * 16, g, t, raw);

    for (; wt < WTILES; wt += wstride) {
        const size_t rowbase = (size_t)wt * 16;

        // ---- build A frags from prefetched raw ----
        uint32_t Ah[16], Al[16];
#pragma unroll
        for (int i = 0; i < 8; i++) pack_hl(raw[i].x, raw[i].y, Ah[i], Al[i]);

        // ---- prefetch next tile's raw x (overlaps with all mma below) ----
        int nwt = wt + wstride;
        if (nwt < WTILES) load_raw(x, (size_t)nwt * 16, g, t, raw);

        float d[8][4];

        // ---- L1: 32 -> 64 ----
#pragma unroll
        for (int j = 0; j < 8; j++)
#pragma unroll
            for (int e = 0; e < 4; e++) d[j][e] = 0.0f;
        layer_mma<2, 8>(d, sf1, *(const uint32_t(*)[8])Ah, *(const uint32_t(*)[8])Al, lane);
        epi_relu(d, sb1, lane, Ah, Al);

        // ---- L2: 64 -> 64 ----
#pragma unroll
        for (int j = 0; j < 8; j++)
#pragma unroll
            for (int e = 0; e < 4; e++) d[j][e] = 0.0f;
        layer_mma<4, 8>(d, sf2, Ah, Al, lane);
        epi_relu(d, sb2, lane, Ah, Al);

        // ---- L3: 64 -> 64 ----
#pragma unroll
        for (int j = 0; j < 8; j++)
#pragma unroll
            for (int e = 0; e < 4; e++) d[j][e] = 0.0f;
        layer_mma<4, 8>(d, sf3, Ah, Al, lane);
        epi_relu(d, sb3, lane, Ah, Al);

        // ---- L4: 64 -> 16 (no relu) ----
        float d4[2][4];
#pragma unroll
        for (int j = 0; j < 2; j++)
#pragma unroll
            for (int e = 0; e < 4; e++) d4[j][e] = 0.0f;
        layer_mma<4, 2>(d4, sf4, Ah, Al, lane);

        // ---- store: rows g, g+8; cols 8j+2t, +1 ----
        {
            float* o0 = out + (rowbase + g) * 16;
            float* o8 = out + (rowbase + g + 8) * 16;
#pragma unroll
            for (int j = 0; j < 2; j++) {
                float2 b = *(const float2*)&sb4[j * 8 + 2 * t];
                *(float2*)&o0[j * 8 + 2 * t] = make_float2(d4[j][0] + b.x, d4[j][1] + b.y);
                *(float2*)&o8[j * 8 + 2 * t] = make_float2(d4[j][2] + b.x, d4[j][3] + b.y);
            }
        }
    }
}

extern "C" void kernel_launch(void* const* d_in, const int* in_sizes, int n_in,
                              void* d_out, int out_size) {
    (void)in_sizes; (void)n_in; (void)out_size;
    const float* x  = (const float*)d_in[0];
    const float* Wi = (const float*)d_in[1];
    const float* bi = (const float*)d_in[2];
    const float* W1 = (const float*)d_in[3];
    const float* b1 = (const float*)d_in[4];
    const float* W2 = (const float*)d_in[5];
    const float* b2 = (const float*)d_in[6];
    const float* Wo = (const float*)d_in[7];
    const float* bo = (const float*)d_in[8];
    float* out = (float*)d_out;

    mlp_hmma_kernel<<<GRID, THREADS>>>(x, Wi, bi, W1, b1, W2, b2, Wo, bo, out);
}